// round 12
// baseline (speedup 1.0000x reference)
#include <cuda_runtime.h>
#include <cuda_fp16.h>
#include <math.h>
#include <stdint.h>

#define NIMG 64
#define C_IN 512
#define C_MID 128
#define HW 784
#define BN_EPS 1e-5f
#define CH_PAD 960   // padded channel: 30 rows x 32 cols

// ---------------------------------------------------------------------------
// Scratch (__device__ globals; no allocations allowed)
// ---------------------------------------------------------------------------
__device__ float  g_w1t[C_IN * C_MID];              // w1 transposed [ci][co], fp32
__device__ __half g_t1p [(size_t)NIMG * C_MID * CH_PAD];
__device__ __half g_t1pm[(size_t)NIMG * C_MID * CH_PAD];   // +1 shifted twin
__device__ __half g_w2h[9 * C_MID * C_MID], g_w2l[9 * C_MID * C_MID];  // 2^11-scaled
__device__ __half g_w3h[C_IN * C_MID], g_w3l[C_IN * C_MID];            // 2^11-scaled
__device__ float g_s1[C_MID], g_h1[C_MID];
__device__ float g_s2[C_MID], g_h2[C_MID];
__device__ float g_s3[C_IN], g_h3[C_IN];

// scheduler state: [0]=conv1 ctr, [1]=conv23 ctr, [2..65]=per-image done count
__device__ int g_sched[2 + NIMG];

#define INV2048 (1.0f / 2048.0f)

// ---------------------------------------------------------------------------
// Helpers
// ---------------------------------------------------------------------------
__device__ __forceinline__ uint32_t smem_u32(const void* p) {
    uint32_t a;
    asm("{ .reg .u64 t; cvta.to.shared.u64 t, %1; cvt.u32.u64 %0, t; }" : "=r"(a) : "l"(p));
    return a;
}
__device__ __forceinline__ uint32_t swz(uint32_t o) { return o ^ ((o >> 3) & 0x70); }

#define CPA16(d, s) asm volatile("cp.async.cg.shared.global [%0], [%1], 16;" :: "r"(d), "l"(s))
#define CPA4(d, s)  asm volatile("cp.async.ca.shared.global [%0], [%1], 4;"  :: "r"(d), "l"(s))
#define CPCOMMIT()  asm volatile("cp.async.commit_group;" ::: "memory")
#define CPWAIT1()   asm volatile("cp.async.wait_group 1;" ::: "memory")
#define CPWAIT0()   asm volatile("cp.async.wait_group 0;" ::: "memory")

__device__ __forceinline__ void ldsm_x4(uint32_t* a, uint32_t addr) {
    asm volatile("ldmatrix.sync.aligned.m8n8.x4.shared.b16 {%0,%1,%2,%3}, [%4];"
                 : "=r"(a[0]), "=r"(a[1]), "=r"(a[2]), "=r"(a[3]) : "r"(addr));
}
__device__ __forceinline__ void ldsm_x2t(uint32_t& b0, uint32_t& b1, uint32_t addr) {
    asm volatile("ldmatrix.sync.aligned.m8n8.x2.trans.shared.b16 {%0,%1}, [%2];"
                 : "=r"(b0), "=r"(b1) : "r"(addr));
}
__device__ __forceinline__ void mma16816(float* c, const uint32_t* a, uint32_t b0, uint32_t b1) {
    asm volatile("mma.sync.aligned.m16n8k16.row.col.f32.f16.f16.f32 "
                 "{%0,%1,%2,%3},{%4,%5,%6,%7},{%8,%9},{%0,%1,%2,%3};"
                 : "+f"(c[0]), "+f"(c[1]), "+f"(c[2]), "+f"(c[3])
                 : "r"(a[0]), "r"(a[1]), "r"(a[2]), "r"(a[3]), "r"(b0), "r"(b1));
}

__device__ __forceinline__ float bfq(float v, float m) {
    if (m <= 0.f) return v;
    int fe = ilogbf(m);
    fe = fe < -4 ? -4 : (fe > 3 ? 3 : fe);
    float inv  = __int_as_float((127 + 3 - fe) << 23);
    float step = __int_as_float((127 - 3 + fe) << 23);
    float r = rintf(v * inv);
    r = fminf(r, 15.f);
    return r * step;
}

// ---------------------------------------------------------------------------
// Prep kernels
// ---------------------------------------------------------------------------
__global__ void bnprep_kernel(
    const float* __restrict__ g1, const float* __restrict__ b1,
    const float* __restrict__ mu1, const float* __restrict__ var1,
    const float* __restrict__ g2, const float* __restrict__ b2,
    const float* __restrict__ mu2, const float* __restrict__ var2,
    const float* __restrict__ g3, const float* __restrict__ b3,
    const float* __restrict__ mu3, const float* __restrict__ var3)
{
    int c = threadIdx.x;
    if (c < C_MID) {
        float inv = g1[c] * rsqrtf(var1[c] + BN_EPS);
        g_s1[c] = inv; g_h1[c] = b1[c] - mu1[c] * inv;
        inv = g2[c] * rsqrtf(var2[c] + BN_EPS);
        g_s2[c] = inv * INV2048; g_h2[c] = b2[c] - mu2[c] * inv;
    }
    if (c < C_IN) {
        float inv = g3[c] * rsqrtf(var3[c] + BN_EPS);
        g_s3[c] = inv * INV2048; g_h3[c] = b3[c] - mu3[c] * inv;
    }
}

__global__ void wprep_k(const float* __restrict__ w1,
                        const float* __restrict__ w2,
                        const float* __restrict__ w3)
{
    int idx = blockIdx.x * blockDim.x + threadIdx.x;
    const int N2 = 9 * C_MID * C_MID, N3 = C_IN * C_MID, N1 = C_IN * C_MID;
    if (idx < N2) {
        int tap = idx / (C_MID * C_MID);
        int r = idx % (C_MID * C_MID);
        int co = r >> 7, ci = r & 127;
        float fs = w2[(size_t)(co * C_MID + ci) * 9 + tap] * 2048.0f;
        __half hi = __float2half_rn(fs);
        g_w2h[idx] = hi; g_w2l[idx] = __float2half_rn(fs - __half2float(hi));
    } else if (idx < N2 + N3) {
        int j = idx - N2;
        float fs = w3[j] * 2048.0f;
        __half hi = __float2half_rn(fs);
        g_w3h[j] = hi; g_w3l[j] = __float2half_rn(fs - __half2float(hi));
    } else if (idx < N2 + N3 + N1) {
        int j = idx - N2 - N3;             // j = ci*128 + co
        int ci = j >> 7, co = j & 127;
        g_w1t[j] = w1[(size_t)co * C_IN + ci];
    }
}

// ---------------------------------------------------------------------------
// conv1 tile (proven R10/R11 body): fp32 GEMM [128x512]@[512x112]
// + BN1 + ReLU + block-FP quant + fp16 padded store (t1p/t1pm).
// smem (floats): a[2][4096] @0, b[2][3584] @8192, bmax(int448) @15360.
// ---------------------------------------------------------------------------
__device__ void conv1_tile(char* smraw, const float* __restrict__ X, int n, int bx)
{
    float* sm = (float*)smraw;
    const uint32_t sbase = smem_u32(sm);
    const uint32_t aB[2] = {sbase, sbase + 16384};
    const uint32_t bB[2] = {sbase + 32768, sbase + 32768 + 14336};
    int* bmaxI = (int*)(sm + 15360);

    const int col0 = bx * 112;
    const float* Bn = X + (size_t)n * C_IN * HW + col0;

    const int t = threadIdx.x;
    const int tx = t & 15, ty = t >> 4;

    const int kkA = t >> 3, sA = t & 7;
    const uint32_t adoff = kkA * 512 + sA * 64;
    const float* asrc0 = g_w1t + kkA * C_MID + sA * 16;
    const int w28 = t % 28, q8 = t / 28;
    const uint32_t bdoff = q8 * 448 + w28 * 16;
    const float* bsrc0 = Bn + (size_t)q8 * HW + w28 * 4;

    for (int i = t; i < 448; i += 256) bmaxI[i] = 0;

    float acc[8][7];
#pragma unroll
    for (int i = 0; i < 8; i++)
#pragma unroll
        for (int j = 0; j < 7; j++) acc[i][j] = 0.f;

    {
        const float* as_ = asrc0;
        uint32_t ad = aB[0] + adoff;
#pragma unroll
        for (int i = 0; i < 4; i++) CPA16(ad + 16 * i, as_ + 4 * i);
        if (t < 224) {
            uint32_t bd = bB[0] + bdoff;
            const float* bs_ = bsrc0;
#pragma unroll
            for (int kk = 0; kk < 4; kk++) CPA16(bd + kk * 3584, bs_ + kk * 8 * HW);
        }
        CPCOMMIT();
    }

    for (int c = 0; c < 16; c++) {
        const int cur = c & 1;
        if (c + 1 < 16) {
            const int nk0 = (c + 1) * 32;
            const float* as_ = asrc0 + (size_t)nk0 * C_MID;
            uint32_t ad = aB[cur ^ 1] + adoff;
#pragma unroll
            for (int i = 0; i < 4; i++) CPA16(ad + 16 * i, as_ + 4 * i);
            if (t < 224) {
                uint32_t bd = bB[cur ^ 1] + bdoff;
                const float* bs_ = bsrc0 + (size_t)nk0 * HW;
#pragma unroll
                for (int kk = 0; kk < 4; kk++) CPA16(bd + kk * 3584, bs_ + kk * 8 * HW);
            }
            CPCOMMIT();
            CPWAIT1();
        } else {
            CPWAIT0();
        }
        __syncthreads();

        const float* a_s = sm + cur * 4096;
        const float* b_s = sm + 8192 + cur * 3584;
#pragma unroll 8
        for (int kk = 0; kk < 32; kk++) {
            float4 a0 = *(const float4*)&a_s[kk * 128 + ty * 8];
            float4 a1 = *(const float4*)&a_s[kk * 128 + ty * 8 + 4];
            float av[8] = {a0.x, a0.y, a0.z, a0.w, a1.x, a1.y, a1.z, a1.w};
            float bv[7];
#pragma unroll
            for (int j = 0; j < 7; j++) bv[j] = b_s[kk * 112 + tx + 16 * j];
#pragma unroll
            for (int i = 0; i < 8; i++)
#pragma unroll
                for (int j = 0; j < 7; j++)
                    acc[i][j] = fmaf(av[i], bv[j], acc[i][j]);
        }
        __syncthreads();
    }

    const int blk = ty >> 2;
    {
        float lm[7];
#pragma unroll
        for (int j = 0; j < 7; j++) lm[j] = 0.f;
#pragma unroll
        for (int i = 0; i < 8; i++) {
            int ch = ty * 8 + i;
            float s = g_s1[ch], h = g_h1[ch];
#pragma unroll
            for (int j = 0; j < 7; j++) {
                float v = fmaxf(fmaf(acc[i][j], s, h), 0.f);
                acc[i][j] = v;
                lm[j] = fmaxf(lm[j], v);
            }
        }
#pragma unroll
        for (int j = 0; j < 7; j++)
            atomicMax(&bmaxI[blk * 112 + tx + 16 * j], __float_as_int(lm[j]));
    }
    __syncthreads();

    const size_t imgB = (size_t)n * C_MID;
#pragma unroll
    for (int j = 0; j < 7; j++) {
        int p = col0 + tx + 16 * j;
        float ma = __int_as_float(bmaxI[blk * 112 + tx + 16 * j]);
        float step = 1.f, inv = 1.f;
        bool doq = (ma > 0.f);
        if (doq) {
            int e;
            frexpf(ma, &e);
            int fe = e - 1;
            if (fe < -4) fe = -4;
            if (fe > 3) fe = 3;
            step = ldexpf(1.0f, fe - 3);
            inv = ldexpf(1.0f, 3 - fe);
        }
        int y = p / 28, xx = p - y * 28;
#pragma unroll
        for (int i = 0; i < 8; i++) {
            float v = acc[i][j];
            if (doq) {
                float r = rintf(v * inv);
                r = fminf(fmaxf(r, -16.f), 15.f);
                v = r * step;
            }
            __half hq = __float2half_rn(v);
            int ch = ty * 8 + i;
            size_t chb = (imgB + ch) * CH_PAD + (size_t)(y + 1) * 32 + xx;
            g_t1p [chb + 2] = hq;
            g_t1pm[chb + 3] = hq;
        }
    }
}

// ---------------------------------------------------------------------------
// HMMA A staging
// ---------------------------------------------------------------------------
__device__ __forceinline__ void stageA2(uint32_t ab, const __half* src,
                                        uint32_t asw, uint32_t ago)
{
    const __half* s = src + ago;
    uint32_t d = ab + asw;
#pragma unroll
    for (int i = 0; i < 4; i++)
        CPA16(d + i * 4096, s + i * 4096);
}

// ---------------------------------------------------------------------------
// conv2+conv3 tile (proven R11 body)
// ---------------------------------------------------------------------------
__device__ void conv23_tile(char* smraw, const float* __restrict__ xres,
                            float* __restrict__ out, int n, int bx)
{
    const uint32_t sbase = smem_u32(smraw);
    const uint32_t sA0 = sbase, sA1 = sbase + 16384;
    const uint32_t sB0 = sbase + 32768, sB1 = sbase + 32768 + 15360;
    const uint32_t t2b = sbase + 32768;

    const int tid = threadIdx.x, wid = tid >> 5, lane = tid & 31;
    const int p0 = bx * 112;

    const int m0 = (wid >> 1) * 32;
    const int n0w = (wid & 1) * 56;

    const uint32_t asw = swz((tid >> 3) * 128 + (tid & 7) * 16);
    const uint32_t ago = (tid >> 3) * C_MID + (tid & 7) * 8;
    const int wq = tid % 14, q = tid / 14;
    const int rimg = q & 3, rk0 = q >> 2;
    const bool bact = (q < 16);
    const uint32_t bdoff = rk0 * 16 * 240 + rimg * 56 + 4 * wq;
    const uint32_t bsoff = rk0 * 16 * CH_PAD + (rimg + 1) * 32 + 2 * wq;

    const int rq = lane >> 2, cq = (lane & 3) * 2;
    const size_t imgB5 = (size_t)n * C_IN;

    float acc[2][7][4];
#pragma unroll
    for (int mt = 0; mt < 2; mt++)
#pragma unroll
        for (int nt = 0; nt < 7; nt++)
#pragma unroll
            for (int e = 0; e < 4; e++) acc[mt][nt][e] = 0.f;

    auto stage2 = [&](int c, uint32_t ab, uint32_t bb) {
        int tap = c >> 2, kc = (c >> 1) & 1, wsel = c & 1;
        const __half* aw = (wsel ? g_w2h : g_w2l) + (size_t)tap * C_MID * C_MID + kc * 64;
        stageA2(ab, aw, asw, ago);
        if (wsel == 0 && bact) {
            int dy = tap / 3 - 1, dx = tap % 3 - 1;
            int y0 = p0 / 28;
            const __half* base = (dx & 1) ? g_t1pm : g_t1p;
            int qoff = (dx & 1) ? dx + 3 : dx + 2;
            const __half* s = base + ((size_t)n * C_MID + kc * 64) * CH_PAD
                            + (y0 + dy) * 32 + qoff + bsoff;
            uint32_t d = bb + bdoff;
#pragma unroll
            for (int kk = 0; kk < 16; kk++)
                CPA4(d + kk * 240, s + kk * CH_PAD);
        }
        CPCOMMIT();
    };
    auto stage3 = [&](int c3, uint32_t ab) {
        int mt = c3 >> 2, kc = (c3 >> 1) & 1, po = c3 & 1;
        const __half* aw = (po ? g_w3h : g_w3l) + (size_t)(mt * 128) * C_MID + kc * 64;
        stageA2(ab, aw, asw, ago);
        CPCOMMIT();
    };

    // ===== Phase A: conv2 =====
    stage2(0, sA0, sB0);

    for (int c = 0; c < 36; c++) {
        const uint32_t cab = (c & 1) ? sA1 : sA0;
        const uint32_t cbb = ((c >> 1) & 1) ? sB1 : sB0;
        if (c + 1 < 36) {
            stage2(c + 1, ((c + 1) & 1) ? sA1 : sA0, (((c + 1) >> 1) & 1) ? sB1 : sB0);
            CPWAIT1();
        } else {
            stage3(0, sA0);
            CPWAIT1();
        }
        __syncthreads();

        const uint32_t bBrow = cbb + (lane & 15) * 240 + n0w * 2;
#pragma unroll
        for (int kk = 0; kk < 4; kk++) {
            uint32_t a[2][4];
#pragma unroll
            for (int mt = 0; mt < 2; mt++) {
                int r = m0 + mt * 16 + (lane & 15);
                int kb = (kk * 16 + ((lane >> 4) << 3)) * 2;
                ldsm_x4(a[mt], cab + swz(r * 128 + kb));
            }
#pragma unroll
            for (int nt = 0; nt < 7; nt++) {
                uint32_t b0, b1;
                ldsm_x2t(b0, b1, bBrow + kk * 3840 + nt * 16);
#pragma unroll
                for (int mt = 0; mt < 2; mt++) mma16816(acc[mt][nt], a[mt], b0, b1);
            }
        }
        __syncthreads();
    }

    // conv2 epilogue -> smem t2 tile
    {
        float sj[4], hj[4];
#pragma unroll
        for (int j = 0; j < 4; j++) {
            int cc = m0 + 8 * j + rq;
            sj[j] = g_s2[cc]; hj[j] = g_h2[cc];
        }
#pragma unroll
        for (int nt = 0; nt < 7; nt++) {
            int c0 = n0w + nt * 8 + cq;
            float v[2][4];
#pragma unroll
            for (int mt = 0; mt < 2; mt++)
#pragma unroll
                for (int e = 0; e < 4; e++) {
                    int j = 2 * mt + (e >> 1);
                    v[mt][e] = fmaxf(fmaf(acc[mt][nt][e], sj[j], hj[j]), 0.f);
                }
            float em = fmaxf(fmaxf(v[0][0], v[0][2]), fmaxf(v[1][0], v[1][2]));
            float om = fmaxf(fmaxf(v[0][1], v[0][3]), fmaxf(v[1][1], v[1][3]));
#pragma unroll
            for (int d = 4; d < 32; d <<= 1) {
                em = fmaxf(em, __shfl_xor_sync(0xffffffffu, em, d));
                om = fmaxf(om, __shfl_xor_sync(0xffffffffu, om, d));
            }
#pragma unroll
            for (int mt = 0; mt < 2; mt++) {
                int cc0 = m0 + 16 * mt + rq;
                __half2 h01 = __halves2half2(__float2half_rn(bfq(v[mt][0], em)),
                                             __float2half_rn(bfq(v[mt][1], om)));
                __half2 h23 = __halves2half2(__float2half_rn(bfq(v[mt][2], em)),
                                             __float2half_rn(bfq(v[mt][3], om)));
                *(__half2*)(smraw + 32768 + cc0 * 240 + c0 * 2) = h01;
                *(__half2*)(smraw + 32768 + (cc0 + 8) * 240 + c0 * 2) = h23;
            }
        }
    }
    __syncthreads();

    // ===== Phase B: conv3 =====
#pragma unroll
    for (int mt = 0; mt < 2; mt++)
#pragma unroll
        for (int nt = 0; nt < 7; nt++)
#pragma unroll
            for (int e = 0; e < 4; e++) acc[mt][nt][e] = 0.f;

    for (int c3 = 0; c3 < 16; c3++) {
        const uint32_t cab = (c3 & 1) ? sA1 : sA0;
        const int kc = (c3 >> 1) & 1;
        const uint32_t cbb = t2b + kc * 15360;
        if (c3 + 1 < 16) {
            stage3(c3 + 1, ((c3 + 1) & 1) ? sA1 : sA0);
            CPWAIT1();
        } else {
            CPWAIT0();
        }
        __syncthreads();

        const uint32_t bBrow = cbb + (lane & 15) * 240 + n0w * 2;
#pragma unroll
        for (int kk = 0; kk < 4; kk++) {
            uint32_t a[2][4];
#pragma unroll
            for (int mt = 0; mt < 2; mt++) {
                int r = m0 + mt * 16 + (lane & 15);
                int kb = (kk * 16 + ((lane >> 4) << 3)) * 2;
                ldsm_x4(a[mt], cab + swz(r * 128 + kb));
            }
#pragma unroll
            for (int nt = 0; nt < 7; nt++) {
                uint32_t b0, b1;
                ldsm_x2t(b0, b1, bBrow + kk * 3840 + nt * 16);
#pragma unroll
                for (int mt = 0; mt < 2; mt++) mma16816(acc[mt][nt], a[mt], b0, b1);
            }
        }
        __syncthreads();

        if ((c3 & 3) == 3) {
            const int mtile = c3 >> 2;
            const int coW = mtile * 128 + m0;
            float sj[4], hj[4];
#pragma unroll
            for (int j = 0; j < 4; j++) {
                int cc = coW + 8 * j + rq;
                sj[j] = g_s3[cc]; hj[j] = g_h3[cc];
            }
#pragma unroll
            for (int nt = 0; nt < 7; nt++) {
                int c0 = n0w + nt * 8 + cq;
                float v[2][4];
#pragma unroll
                for (int mt = 0; mt < 2; mt++)
#pragma unroll
                    for (int e = 0; e < 4; e++) {
                        int j = 2 * mt + (e >> 1);
                        v[mt][e] = fmaf(acc[mt][nt][e], sj[j], hj[j]);
                    }
#pragma unroll
                for (int mt = 0; mt < 2; mt++) {
                    int r1 = coW + 16 * mt + rq;
                    float2 ra = *(const float2*)(xres + (imgB5 + r1) * HW + p0 + c0);
                    float2 rb = *(const float2*)(xres + (imgB5 + r1 + 8) * HW + p0 + c0);
                    v[mt][0] += ra.x; v[mt][1] += ra.y;
                    v[mt][2] += rb.x; v[mt][3] += rb.y;
                }
#pragma unroll
                for (int mt = 0; mt < 2; mt++)
#pragma unroll
                    for (int e = 0; e < 4; e++) v[mt][e] = fmaxf(v[mt][e], 0.f);

                float em = fmaxf(fmaxf(v[0][0], v[0][2]), fmaxf(v[1][0], v[1][2]));
                float om = fmaxf(fmaxf(v[0][1], v[0][3]), fmaxf(v[1][1], v[1][3]));
#pragma unroll
                for (int d = 4; d < 32; d <<= 1) {
                    em = fmaxf(em, __shfl_xor_sync(0xffffffffu, em, d));
                    om = fmaxf(om, __shfl_xor_sync(0xffffffffu, om, d));
                }
#pragma unroll
                for (int mt = 0; mt < 2; mt++) {
                    int r1 = coW + 16 * mt + rq;
                    float2 o1, o2;
                    o1.x = bfq(v[mt][0], em); o1.y = bfq(v[mt][1], om);
                    o2.x = bfq(v[mt][2], em); o2.y = bfq(v[mt][3], om);
                    *(float2*)(out + (imgB5 + r1) * HW + p0 + c0) = o1;
                    *(float2*)(out + (imgB5 + r1 + 8) * HW + p0 + c0) = o2;
                }
            }
#pragma unroll
            for (int mt = 0; mt < 2; mt++)
#pragma unroll
                for (int nt = 0; nt < 7; nt++)
#pragma unroll
                    for (int e = 0; e < 4; e++) acc[mt][nt][e] = 0.f;
        }
    }
}

// ---------------------------------------------------------------------------
// Persistent mega-kernel with work-stealing scheduler.
// Phase 1: 448 conv1 tiles (image-major). Phase 2: 448 conv23 tiles, each
// spinning until its image's 7 conv1 tiles are done. Deadlock-free for any
// residency: claims are dynamic, so spinners only wait on resident workers.
// ---------------------------------------------------------------------------
__global__ __launch_bounds__(256, 3) void mega_k(const float* __restrict__ x,
                                                 float* __restrict__ out)
{
    extern __shared__ __align__(1024) char smraw[];
    __shared__ int s_item;
    const int tid = threadIdx.x;

    // ---- Phase 1: conv1 tiles ----
    for (;;) {
        if (tid == 0) s_item = atomicAdd(&g_sched[0], 1);
        __syncthreads();
        int it = s_item;
        __syncthreads();
        if (it >= 448) break;
        conv1_tile(smraw, x, it / 7, it % 7);
        if (tid == 0) {
            __threadfence();
            atomicAdd(&g_sched[2 + it / 7], 1);
        }
    }

    // ---- Phase 2: conv23 tiles ----
    for (;;) {
        if (tid == 0) s_item = atomicAdd(&g_sched[1], 1);
        __syncthreads();
        int it = s_item;
        __syncthreads();
        if (it >= 448) break;
        int n = it / 7;
        if (tid == 0) {
            volatile int* p = &g_sched[2 + n];
            while (*p < 7) __nanosleep(200);
            __threadfence();
        }
        __syncthreads();
        conv23_tile(smraw, x, out, n, it % 7);
    }
}

// ---------------------------------------------------------------------------
// Launcher
// ---------------------------------------------------------------------------
extern "C" void kernel_launch(void* const* d_in, const int* in_sizes, int n_in,
                              void* d_out, int out_size)
{
    (void)n_in; (void)out_size;

    int iw1, iw2, iw3, ibn1, ibn2, ibn3;
    if (in_sizes[2] == 147456) {
        iw1 = 1; iw2 = 2; iw3 = 3; ibn1 = 4; ibn2 = 8; ibn3 = 12;
    } else {
        iw1 = 1; ibn1 = 2; iw2 = 6; ibn2 = 7; iw3 = 11; ibn3 = 12;
    }

    const float* x  = (const float*)d_in[0];
    const float* w1 = (const float*)d_in[iw1];
    const float* w2 = (const float*)d_in[iw2];
    const float* w3 = (const float*)d_in[iw3];
    const float* g1 = (const float*)d_in[ibn1 + 0];
    const float* b1 = (const float*)d_in[ibn1 + 1];
    const float* mu1 = (const float*)d_in[ibn1 + 2];
    const float* var1 = (const float*)d_in[ibn1 + 3];
    const float* g2 = (const float*)d_in[ibn2 + 0];
    const float* b2 = (const float*)d_in[ibn2 + 1];
    const float* mu2 = (const float*)d_in[ibn2 + 2];
    const float* var2 = (const float*)d_in[ibn2 + 3];
    const float* g3 = (const float*)d_in[ibn3 + 0];
    const float* b3 = (const float*)d_in[ibn3 + 1];
    const float* mu3 = (const float*)d_in[ibn3 + 2];
    const float* var3 = (const float*)d_in[ibn3 + 3];
    float* out = (float*)d_out;

    void* schedp;
    cudaGetSymbolAddress(&schedp, g_sched);

    const int SMEM = 63488;
    cudaFuncSetAttribute(mega_k, cudaFuncAttributeMaxDynamicSharedMemorySize, SMEM);

    // reset scheduler state (graph-capturable)
    cudaMemsetAsync(schedp, 0, sizeof(int) * (2 + NIMG));

    bnprep_kernel<<<1, 512>>>(g1, b1, mu1, var1, g2, b2, mu2, var2, g3, b3, mu3, var3);
    {
        int total = 9 * C_MID * C_MID + 2 * C_IN * C_MID;
        wprep_k<<<(total + 255) / 256, 256>>>(w1, w2, w3);
    }

    mega_k<<<448, 256, SMEM>>>(x, out);
}

// round 13
// speedup vs baseline: 1.0550x; 1.0550x over previous
#include <cuda_runtime.h>
#include <cuda_fp16.h>
#include <math.h>
#include <stdint.h>

#define NIMG 64
#define C_IN 512
#define C_MID 128
#define HW 784
#define BN_EPS 1e-5f
#define CH_PAD 960   // padded channel: 30 rows x 32 cols

// ---------------------------------------------------------------------------
// Scratch (__device__ globals; no allocations allowed)
// ---------------------------------------------------------------------------
__device__ float  g_w1t[C_IN * C_MID];              // w1 transposed [ci][co], fp32
__device__ __half g_t1p [(size_t)NIMG * C_MID * CH_PAD];
__device__ __half g_t1pm[(size_t)NIMG * C_MID * CH_PAD];   // +1 shifted twin
__device__ __half g_w2h[9 * C_MID * C_MID], g_w2l[9 * C_MID * C_MID];  // 2^11-scaled
__device__ __half g_w3h[C_IN * C_MID], g_w3l[C_IN * C_MID];            // 2^11-scaled
__device__ float g_s1[C_MID], g_h1[C_MID];
__device__ float g_s2[C_MID], g_h2[C_MID];
__device__ float g_s3[C_IN], g_h3[C_IN];

#define INV2048 (1.0f / 2048.0f)

// ---------------------------------------------------------------------------
// Helpers
// ---------------------------------------------------------------------------
__device__ __forceinline__ uint32_t smem_u32(const void* p) {
    uint32_t a;
    asm("{ .reg .u64 t; cvta.to.shared.u64 t, %1; cvt.u32.u64 %0, t; }" : "=r"(a) : "l"(p));
    return a;
}
__device__ __forceinline__ uint32_t swz(uint32_t o) { return o ^ ((o >> 3) & 0x70); }

#define CPA16(d, s) asm volatile("cp.async.cg.shared.global [%0], [%1], 16;" :: "r"(d), "l"(s))
#define CPA4(d, s)  asm volatile("cp.async.ca.shared.global [%0], [%1], 4;"  :: "r"(d), "l"(s))
#define CPCOMMIT()  asm volatile("cp.async.commit_group;" ::: "memory")
#define CPWAIT1()   asm volatile("cp.async.wait_group 1;" ::: "memory")
#define CPWAIT0()   asm volatile("cp.async.wait_group 0;" ::: "memory")

__device__ __forceinline__ void ldsm_x4(uint32_t* a, uint32_t addr) {
    asm volatile("ldmatrix.sync.aligned.m8n8.x4.shared.b16 {%0,%1,%2,%3}, [%4];"
                 : "=r"(a[0]), "=r"(a[1]), "=r"(a[2]), "=r"(a[3]) : "r"(addr));
}
__device__ __forceinline__ void ldsm_x4t(uint32_t& b0, uint32_t& b1,
                                         uint32_t& b2, uint32_t& b3, uint32_t addr) {
    asm volatile("ldmatrix.sync.aligned.m8n8.x4.trans.shared.b16 {%0,%1,%2,%3}, [%4];"
                 : "=r"(b0), "=r"(b1), "=r"(b2), "=r"(b3) : "r"(addr));
}
__device__ __forceinline__ void mma16816(float* c, const uint32_t* a, uint32_t b0, uint32_t b1) {
    asm volatile("mma.sync.aligned.m16n8k16.row.col.f32.f16.f16.f32 "
                 "{%0,%1,%2,%3},{%4,%5,%6,%7},{%8,%9},{%0,%1,%2,%3};"
                 : "+f"(c[0]), "+f"(c[1]), "+f"(c[2]), "+f"(c[3])
                 : "r"(a[0]), "r"(a[1]), "r"(a[2]), "r"(a[3]), "r"(b0), "r"(b1));
}

// Block floating point quant: m = block max (>=0), v >= 0.
__device__ __forceinline__ float bfq(float v, float m) {
    if (m <= 0.f) return v;
    int fe = ilogbf(m);
    fe = fe < -4 ? -4 : (fe > 3 ? 3 : fe);
    float inv  = __int_as_float((127 + 3 - fe) << 23);
    float step = __int_as_float((127 - 3 + fe) << 23);
    float r = rintf(v * inv);
    r = fminf(r, 15.f);
    return r * step;
}

// ---------------------------------------------------------------------------
// Combined prep: BN folds + weight splits + w1 transpose
// ---------------------------------------------------------------------------
__global__ void prep_k(const float* __restrict__ w1,
                       const float* __restrict__ w2,
                       const float* __restrict__ w3,
                       const float* __restrict__ g1, const float* __restrict__ b1,
                       const float* __restrict__ mu1, const float* __restrict__ var1,
                       const float* __restrict__ g2, const float* __restrict__ b2,
                       const float* __restrict__ mu2, const float* __restrict__ var2,
                       const float* __restrict__ g3, const float* __restrict__ b3,
                       const float* __restrict__ mu3, const float* __restrict__ var3)
{
    int idx = blockIdx.x * blockDim.x + threadIdx.x;
    if (idx < C_IN) {
        if (idx < C_MID) {
            float inv = g1[idx] * rsqrtf(var1[idx] + BN_EPS);
            g_s1[idx] = inv; g_h1[idx] = b1[idx] - mu1[idx] * inv;
            inv = g2[idx] * rsqrtf(var2[idx] + BN_EPS);
            g_s2[idx] = inv * INV2048; g_h2[idx] = b2[idx] - mu2[idx] * inv;
        }
        float inv = g3[idx] * rsqrtf(var3[idx] + BN_EPS);
        g_s3[idx] = inv * INV2048; g_h3[idx] = b3[idx] - mu3[idx] * inv;
    }

    const int N2 = 9 * C_MID * C_MID, N3 = C_IN * C_MID, N1 = C_IN * C_MID;
    if (idx < N2) {
        int tap = idx / (C_MID * C_MID);
        int r = idx % (C_MID * C_MID);
        int co = r >> 7, ci = r & 127;
        float fs = w2[(size_t)(co * C_MID + ci) * 9 + tap] * 2048.0f;
        __half hi = __float2half_rn(fs);
        g_w2h[idx] = hi; g_w2l[idx] = __float2half_rn(fs - __half2float(hi));
    } else if (idx < N2 + N3) {
        int j = idx - N2;
        float fs = w3[j] * 2048.0f;
        __half hi = __float2half_rn(fs);
        g_w3h[j] = hi; g_w3l[j] = __float2half_rn(fs - __half2float(hi));
    } else if (idx < N2 + N3 + N1) {
        int j = idx - N2 - N3;             // j = ci*128 + co
        int ci = j >> 7, co = j & 127;
        g_w1t[j] = w1[(size_t)co * C_IN + ci];
    }
}

// ---------------------------------------------------------------------------
// conv1 fused (proven): fp32 GEMM [128x512]@[512x112] per CTA, cp.async, occ3
// + BN1 + ReLU + block-FP quant + fp16 padded store (t1p/t1pm).
// ---------------------------------------------------------------------------
__global__ __launch_bounds__(256, 3)
void conv1_fused_k(const float* __restrict__ B,
                   const float* __restrict__ scale, const float* __restrict__ shift)
{
    extern __shared__ __align__(16) float sm[];
    const uint32_t sbase = smem_u32(sm);
    const uint32_t aB[2] = {sbase, sbase + 16384};
    const uint32_t bB[2] = {sbase + 32768, sbase + 32768 + 14336};
    int* bmaxI = (int*)(sm + 15360);

    const int n = blockIdx.y;
    const int col0 = blockIdx.x * 112;
    const float* Bn = B + (size_t)n * C_IN * HW + col0;

    const int t = threadIdx.x;
    const int tx = t & 15, ty = t >> 4;

    const int kkA = t >> 3, sA = t & 7;
    const uint32_t adoff = kkA * 512 + sA * 64;
    const float* asrc0 = g_w1t + kkA * C_MID + sA * 16;
    const int w28 = t % 28, q8 = t / 28;
    const uint32_t bdoff = q8 * 448 + w28 * 16;
    const float* bsrc0 = Bn + (size_t)q8 * HW + w28 * 4;

    for (int i = t; i < 448; i += 256) bmaxI[i] = 0;

    float acc[8][7];
#pragma unroll
    for (int i = 0; i < 8; i++)
#pragma unroll
        for (int j = 0; j < 7; j++) acc[i][j] = 0.f;

    {
        const float* as_ = asrc0;
        uint32_t ad = aB[0] + adoff;
#pragma unroll
        for (int i = 0; i < 4; i++) CPA16(ad + 16 * i, as_ + 4 * i);
        if (t < 224) {
            uint32_t bd = bB[0] + bdoff;
            const float* bs_ = bsrc0;
#pragma unroll
            for (int kk = 0; kk < 4; kk++) CPA16(bd + kk * 3584, bs_ + kk * 8 * HW);
        }
        CPCOMMIT();
    }

    for (int c = 0; c < 16; c++) {
        const int cur = c & 1;
        if (c + 1 < 16) {
            const int nk0 = (c + 1) * 32;
            const float* as_ = asrc0 + (size_t)nk0 * C_MID;
            uint32_t ad = aB[cur ^ 1] + adoff;
#pragma unroll
            for (int i = 0; i < 4; i++) CPA16(ad + 16 * i, as_ + 4 * i);
            if (t < 224) {
                uint32_t bd = bB[cur ^ 1] + bdoff;
                const float* bs_ = bsrc0 + (size_t)nk0 * HW;
#pragma unroll
                for (int kk = 0; kk < 4; kk++) CPA16(bd + kk * 3584, bs_ + kk * 8 * HW);
            }
            CPCOMMIT();
            CPWAIT1();
        } else {
            CPWAIT0();
        }
        __syncthreads();

        const float* a_s = sm + cur * 4096;
        const float* b_s = sm + 8192 + cur * 3584;
#pragma unroll 8
        for (int kk = 0; kk < 32; kk++) {
            float4 a0 = *(const float4*)&a_s[kk * 128 + ty * 8];
            float4 a1 = *(const float4*)&a_s[kk * 128 + ty * 8 + 4];
            float av[8] = {a0.x, a0.y, a0.z, a0.w, a1.x, a1.y, a1.z, a1.w};
            float bv[7];
#pragma unroll
            for (int j = 0; j < 7; j++) bv[j] = b_s[kk * 112 + tx + 16 * j];
#pragma unroll
            for (int i = 0; i < 8; i++)
#pragma unroll
                for (int j = 0; j < 7; j++)
                    acc[i][j] = fmaf(av[i], bv[j], acc[i][j]);
        }
        __syncthreads();
    }

    const int blk = ty >> 2;
    {
        float lm[7];
#pragma unroll
        for (int j = 0; j < 7; j++) lm[j] = 0.f;
#pragma unroll
        for (int i = 0; i < 8; i++) {
            int ch = ty * 8 + i;
            float s = scale[ch], h = shift[ch];
#pragma unroll
            for (int j = 0; j < 7; j++) {
                float v = fmaxf(fmaf(acc[i][j], s, h), 0.f);
                acc[i][j] = v;
                lm[j] = fmaxf(lm[j], v);
            }
        }
#pragma unroll
        for (int j = 0; j < 7; j++)
            atomicMax(&bmaxI[blk * 112 + tx + 16 * j], __float_as_int(lm[j]));
    }
    __syncthreads();

    const size_t imgB = (size_t)n * C_MID;
#pragma unroll
    for (int j = 0; j < 7; j++) {
        int p = col0 + tx + 16 * j;
        float ma = __int_as_float(bmaxI[blk * 112 + tx + 16 * j]);
        float step = 1.f, inv = 1.f;
        bool doq = (ma > 0.f);
        if (doq) {
            int e;
            frexpf(ma, &e);
            int fe = e - 1;
            if (fe < -4) fe = -4;
            if (fe > 3) fe = 3;
            step = ldexpf(1.0f, fe - 3);
            inv = ldexpf(1.0f, 3 - fe);
        }
        int y = p / 28, xx = p - y * 28;
#pragma unroll
        for (int i = 0; i < 8; i++) {
            float v = acc[i][j];
            if (doq) {
                float r = rintf(v * inv);
                r = fminf(fmaxf(r, -16.f), 15.f);
                v = r * step;
            }
            __half hq = __float2half_rn(v);
            int ch = ty * 8 + i;
            size_t chb = (imgB + ch) * CH_PAD + (size_t)(y + 1) * 32 + xx;
            g_t1p [chb + 2] = hq;
            g_t1pm[chb + 3] = hq;
        }
    }
}

// ---------------------------------------------------------------------------
// HMMA A staging
// ---------------------------------------------------------------------------
__device__ __forceinline__ void stageA2(uint32_t ab, const __half* src,
                                        uint32_t asw, uint32_t ago)
{
    const __half* s = src + ago;
    uint32_t d = ab + asw;
#pragma unroll
    for (int i = 0; i < 4; i++)
        CPA16(d + i * 4096, s + i * 4096);
}

// ---------------------------------------------------------------------------
// Fused conv2 + conv3 kernel (R11 structure; B-loads via ldmatrix.x4.trans)
// ---------------------------------------------------------------------------
__global__ __launch_bounds__(256, 3) void conv23_k(const float* __restrict__ xres,
                                                   float* __restrict__ out)
{
    extern __shared__ __align__(1024) char smraw[];
    const uint32_t sbase = smem_u32(smraw);
    const uint32_t sA0 = sbase, sA1 = sbase + 16384;
    const uint32_t sB0 = sbase + 32768, sB1 = sbase + 32768 + 15360;
    const uint32_t t2b = sbase + 32768;          // conv3 B tile aliases B buffers

    const int tid = threadIdx.x, wid = tid >> 5, lane = tid & 31;
    const int bx = blockIdx.x, p0 = bx * 112;
    const int n = blockIdx.y;

    const int m0 = (wid >> 1) * 32;
    const int n0w = (wid & 1) * 56;

    const uint32_t asw = swz((tid >> 3) * 128 + (tid & 7) * 16);
    const uint32_t ago = (tid >> 3) * C_MID + (tid & 7) * 8;
    const int wq = tid % 14, q = tid / 14;
    const int rimg = q & 3, rk0 = q >> 2;
    const bool bact = (q < 16);
    const uint32_t bdoff = rk0 * 16 * 240 + rimg * 56 + 4 * wq;
    const uint32_t bsoff = rk0 * 16 * CH_PAD + (rimg + 1) * 32 + 2 * wq;

    const int rq = lane >> 2, cq = (lane & 3) * 2;
    const size_t imgB5 = (size_t)n * C_IN;
    // x4.trans B base: lanes 16-31 address the +16B (next nt group) neighbor
    const uint32_t bxtra = ((lane >> 4) << 4) + (lane & 15) * 240 + n0w * 2;

    float acc[2][7][4];
#pragma unroll
    for (int mt = 0; mt < 2; mt++)
#pragma unroll
        for (int nt = 0; nt < 7; nt++)
#pragma unroll
            for (int e = 0; e < 4; e++) acc[mt][nt][e] = 0.f;

    auto stage2 = [&](int c, uint32_t ab, uint32_t bb) {
        int tap = c >> 2, kc = (c >> 1) & 1, wsel = c & 1;
        const __half* aw = (wsel ? g_w2h : g_w2l) + (size_t)tap * C_MID * C_MID + kc * 64;
        stageA2(ab, aw, asw, ago);
        if (wsel == 0 && bact) {
            int dy = tap / 3 - 1, dx = tap % 3 - 1;
            int y0 = p0 / 28;
            const __half* base = (dx & 1) ? g_t1pm : g_t1p;
            int qoff = (dx & 1) ? dx + 3 : dx + 2;
            const __half* s = base + ((size_t)n * C_MID + kc * 64) * CH_PAD
                            + (y0 + dy) * 32 + qoff + bsoff;
            uint32_t d = bb + bdoff;
#pragma unroll
            for (int kk = 0; kk < 16; kk++)
                CPA4(d + kk * 240, s + kk * CH_PAD);
        }
        CPCOMMIT();
    };
    auto stage3 = [&](int c3, uint32_t ab) {
        int mt = c3 >> 2, kc = (c3 >> 1) & 1, po = c3 & 1;
        const __half* aw = (po ? g_w3h : g_w3l) + (size_t)(mt * 128) * C_MID + kc * 64;
        stageA2(ab, aw, asw, ago);
        CPCOMMIT();
    };

    // shared compute-chunk body: A from cab, B (x4.trans pairs) from cbb
    auto chunk_mma = [&](uint32_t cab, uint32_t cbb) {
        const uint32_t bBrow = cbb + bxtra;
#pragma unroll
        for (int kk = 0; kk < 4; kk++) {
            uint32_t a[2][4];
#pragma unroll
            for (int mt = 0; mt < 2; mt++) {
                int r = m0 + mt * 16 + (lane & 15);
                int kb = (kk * 16 + ((lane >> 4) << 3)) * 2;
                ldsm_x4(a[mt], cab + swz(r * 128 + kb));
            }
#pragma unroll
            for (int np = 0; np < 4; np++) {
                uint32_t b0, b1, b2, b3;
                ldsm_x4t(b0, b1, b2, b3, bBrow + kk * 3840 + np * 32);
                mma16816(acc[0][2 * np], a[0], b0, b1);
                mma16816(acc[1][2 * np], a[1], b0, b1);
                if (np < 3) {
                    mma16816(acc[0][2 * np + 1], a[0], b2, b3);
                    mma16816(acc[1][2 * np + 1], a[1], b2, b3);
                }
            }
        }
    };

    // ================= Phase 1: conv2 =================
    stage2(0, sA0, sB0);

    for (int c = 0; c < 36; c++) {
        const uint32_t cab = (c & 1) ? sA1 : sA0;
        const uint32_t cbb = ((c >> 1) & 1) ? sB1 : sB0;
        if (c + 1 < 36) {
            stage2(c + 1, ((c + 1) & 1) ? sA1 : sA0, (((c + 1) >> 1) & 1) ? sB1 : sB0);
            CPWAIT1();
        } else {
            stage3(0, sA0);       // prefetch conv3 chunk 0 (conv2 ends on sA1)
            CPWAIT1();
        }
        __syncthreads();
        chunk_mma(cab, cbb);
        __syncthreads();
    }

    // ---- conv2 epilogue: BN2 + ReLU + quant -> smem t2 tile
    {
        float sj[4], hj[4];
#pragma unroll
        for (int j = 0; j < 4; j++) {
            int cc = m0 + 8 * j + rq;
            sj[j] = g_s2[cc]; hj[j] = g_h2[cc];
        }
#pragma unroll
        for (int nt = 0; nt < 7; nt++) {
            int c0 = n0w + nt * 8 + cq;
            float v[2][4];
#pragma unroll
            for (int mt = 0; mt < 2; mt++)
#pragma unroll
                for (int e = 0; e < 4; e++) {
                    int j = 2 * mt + (e >> 1);
                    v[mt][e] = fmaxf(fmaf(acc[mt][nt][e], sj[j], hj[j]), 0.f);
                }
            float em = fmaxf(fmaxf(v[0][0], v[0][2]), fmaxf(v[1][0], v[1][2]));
            float om = fmaxf(fmaxf(v[0][1], v[0][3]), fmaxf(v[1][1], v[1][3]));
#pragma unroll
            for (int d = 4; d < 32; d <<= 1) {
                em = fmaxf(em, __shfl_xor_sync(0xffffffffu, em, d));
                om = fmaxf(om, __shfl_xor_sync(0xffffffffu, om, d));
            }
#pragma unroll
            for (int mt = 0; mt < 2; mt++) {
                int cc0 = m0 + 16 * mt + rq;
                __half2 h01 = __halves2half2(__float2half_rn(bfq(v[mt][0], em)),
                                             __float2half_rn(bfq(v[mt][1], om)));
                __half2 h23 = __halves2half2(__float2half_rn(bfq(v[mt][2], em)),
                                             __float2half_rn(bfq(v[mt][3], om)));
                *(__half2*)(smraw + 32768 + cc0 * 240 + c0 * 2) = h01;
                *(__half2*)(smraw + 32768 + (cc0 + 8) * 240 + c0 * 2) = h23;
            }
        }
    }
    __syncthreads();

    // ================= Phase 2: conv3 =================
#pragma unroll
    for (int mt = 0; mt < 2; mt++)
#pragma unroll
        for (int nt = 0; nt < 7; nt++)
#pragma unroll
            for (int e = 0; e < 4; e++) acc[mt][nt][e] = 0.f;

    for (int c3 = 0; c3 < 16; c3++) {
        const uint32_t cab = (c3 & 1) ? sA1 : sA0;
        const int kc = (c3 >> 1) & 1;
        const uint32_t cbb = t2b + kc * 15360;
        if (c3 + 1 < 16) {
            stage3(c3 + 1, ((c3 + 1) & 1) ? sA1 : sA0);
            CPWAIT1();
        } else {
            CPWAIT0();
        }
        __syncthreads();
        chunk_mma(cab, cbb);
        __syncthreads();

        if ((c3 & 3) == 3) {
            const int mtile = c3 >> 2;
            const int coW = mtile * 128 + m0;
            float sj[4], hj[4];
#pragma unroll
            for (int j = 0; j < 4; j++) {
                int cc = coW + 8 * j + rq;
                sj[j] = g_s3[cc]; hj[j] = g_h3[cc];
            }
#pragma unroll
            for (int nt = 0; nt < 7; nt++) {
                int c0 = n0w + nt * 8 + cq;
                float v[2][4];
#pragma unroll
                for (int mt = 0; mt < 2; mt++)
#pragma unroll
                    for (int e = 0; e < 4; e++) {
                        int j = 2 * mt + (e >> 1);
                        v[mt][e] = fmaf(acc[mt][nt][e], sj[j], hj[j]);
                    }
#pragma unroll
                for (int mt = 0; mt < 2; mt++) {
                    int r1 = coW + 16 * mt + rq;
                    float2 ra = *(const float2*)(xres + (imgB5 + r1) * HW + p0 + c0);
                    float2 rb = *(const float2*)(xres + (imgB5 + r1 + 8) * HW + p0 + c0);
                    v[mt][0] += ra.x; v[mt][1] += ra.y;
                    v[mt][2] += rb.x; v[mt][3] += rb.y;
                }
#pragma unroll
                for (int mt = 0; mt < 2; mt++)
#pragma unroll
                    for (int e = 0; e < 4; e++) v[mt][e] = fmaxf(v[mt][e], 0.f);

                float em = fmaxf(fmaxf(v[0][0], v[0][2]), fmaxf(v[1][0], v[1][2]));
                float om = fmaxf(fmaxf(v[0][1], v[0][3]), fmaxf(v[1][1], v[1][3]));
#pragma unroll
                for (int d = 4; d < 32; d <<= 1) {
                    em = fmaxf(em, __shfl_xor_sync(0xffffffffu, em, d));
                    om = fmaxf(om, __shfl_xor_sync(0xffffffffu, om, d));
                }
#pragma unroll
                for (int mt = 0; mt < 2; mt++) {
                    int r1 = coW + 16 * mt + rq;
                    float2 o1, o2;
                    o1.x = bfq(v[mt][0], em); o1.y = bfq(v[mt][1], om);
                    o2.x = bfq(v[mt][2], em); o2.y = bfq(v[mt][3], om);
                    *(float2*)(out + (imgB5 + r1) * HW + p0 + c0) = o1;
                    *(float2*)(out + (imgB5 + r1 + 8) * HW + p0 + c0) = o2;
                }
            }
#pragma unroll
            for (int mt = 0; mt < 2; mt++)
#pragma unroll
                for (int nt = 0; nt < 7; nt++)
#pragma unroll
                    for (int e = 0; e < 4; e++) acc[mt][nt][e] = 0.f;
        }
    }
}

// ---------------------------------------------------------------------------
// Launcher
// ---------------------------------------------------------------------------
extern "C" void kernel_launch(void* const* d_in, const int* in_sizes, int n_in,
                              void* d_out, int out_size)
{
    (void)n_in; (void)out_size;

    int iw1, iw2, iw3, ibn1, ibn2, ibn3;
    if (in_sizes[2] == 147456) {
        iw1 = 1; iw2 = 2; iw3 = 3; ibn1 = 4; ibn2 = 8; ibn3 = 12;
    } else {
        iw1 = 1; ibn1 = 2; iw2 = 6; ibn2 = 7; iw3 = 11; ibn3 = 12;
    }

    const float* x  = (const float*)d_in[0];
    const float* w1 = (const float*)d_in[iw1];
    const float* w2 = (const float*)d_in[iw2];
    const float* w3 = (const float*)d_in[iw3];
    const float* g1 = (const float*)d_in[ibn1 + 0];
    const float* b1 = (const float*)d_in[ibn1 + 1];
    const float* mu1 = (const float*)d_in[ibn1 + 2];
    const float* var1 = (const float*)d_in[ibn1 + 3];
    const float* g2 = (const float*)d_in[ibn2 + 0];
    const float* b2 = (const float*)d_in[ibn2 + 1];
    const float* mu2 = (const float*)d_in[ibn2 + 2];
    const float* var2 = (const float*)d_in[ibn2 + 3];
    const float* g3 = (const float*)d_in[ibn3 + 0];
    const float* b3 = (const float*)d_in[ibn3 + 1];
    const float* mu3 = (const float*)d_in[ibn3 + 2];
    const float* var3 = (const float*)d_in[ibn3 + 3];
    float* out = (float*)d_out;

    float *s1, *h1;
    cudaGetSymbolAddress((void**)&s1, g_s1);
    cudaGetSymbolAddress((void**)&h1, g_h1);

    const int SMEM = 63488;
    const int SMEM1 = 63232;
    cudaFuncSetAttribute(conv23_k, cudaFuncAttributeMaxDynamicSharedMemorySize, SMEM);
    cudaFuncSetAttribute(conv1_fused_k, cudaFuncAttributeMaxDynamicSharedMemorySize, SMEM1);

    {
        int total = 9 * C_MID * C_MID + 2 * C_IN * C_MID;
        prep_k<<<(total + 255) / 256, 256>>>(w1, w2, w3,
                                             g1, b1, mu1, var1,
                                             g2, b2, mu2, var2,
                                             g3, b3, mu3, var3);
    }

    // conv1 fp32 + BN1 + ReLU + quant + fp16 padded store (cp.async, occ3)
    conv1_fused_k<<<dim3(7, NIMG), 256, SMEM1>>>(x, s1, h1);

    // fused conv2 + conv3
    conv23_k<<<dim3(7, NIMG), 256, SMEM>>>(x, out);
}